// round 10
// baseline (speedup 1.0000x reference)
#include <cuda_runtime.h>

// HyperComplexAdapterBlock: y = phm_up(gelu_new(phm_down(x))), rank-1 PHM.
// R10 = R6/R9 input pipeline + DIRECT coalesced output (out-stage deleted):
// lane l stores f4 f = l+32j straight to gmem; tU[c][i] fetched by one
// variable-source SHFL from group c (tU is group-uniform after butterfly);
// Ru and bu pre-replicated per (j,lane) into granule-consecutive smem
// tables (1 wavefront per read). Removes the 48 wf/token out-stage round
// trip + 24 wf/token bias LDG that kept L1 the cap (70%). TPI=2 so the
// +15KB tables still fit 5 CTAs/SM (45KB smem/CTA).

typedef unsigned long long u64;

__device__ __forceinline__ u64 fma2(u64 a, u64 b, u64 c) {
    u64 d;
    asm("fma.rn.f32x2 %0, %1, %2, %3;" : "=l"(d) : "l"(a), "l"(b), "l"(c));
    return d;
}
__device__ __forceinline__ u64 pk2(float lo, float hi) {
    u64 r; asm("mov.b64 %0, {%1, %2};" : "=l"(r) : "f"(lo), "f"(hi));
    return r;
}
__device__ __forceinline__ float sum2(u64 v) {
    float a, b; asm("mov.b64 {%0, %1}, %2;" : "=f"(a), "=f"(b) : "l"(v));
    return a + b;
}
__device__ __forceinline__ float tanh_fast(float x) {
    float y; asm("tanh.approx.f32 %0, %1;" : "=f"(y) : "f"(x));
    return y;
}

#define NW 4          // warps per CTA
#define NT 128        // threads per CTA
#define TPI 2         // tokens per warp-iteration
#define SW(f) ((f) ^ (((f) >> 3) & 1))

// dynamic smem layout (bytes)
#define OFF_STG   0
#define SZ_STG    (NW * TPI * 192 * 16)           // 24576
#define OFF_PLD   (OFF_STG + SZ_STG)              // 192 f4 k-innermost
#define OFF_PRL   (OFF_PLD + 3072)                // 192 float2 (Rd,Lu) k-inner
#define OFF_RUC   (OFF_PRL + 1536)                // 768 f4 lane-replicated Ru
#define OFF_BUC   (OFF_RUC + 12288)               // 192 f4 lane-replicated bu
#define OFF_RRD   (OFF_BUC + 3072)                // 64 f rule_d
#define OFF_RRU   (OFF_RRD + 256)                 // 64 f rule_u
#define SMEM_TOTAL (OFF_RRU + 256)                // 45056

__global__ __launch_bounds__(NT, 5)
void phm_fused_kernel(const float* __restrict__ x,
                      const float* __restrict__ rule_d,
                      const float* __restrict__ Ld,
                      const float* __restrict__ Rd,
                      const float* __restrict__ bd,
                      const float* __restrict__ rule_u,
                      const float* __restrict__ Lu,
                      const float* __restrict__ Ru,
                      const float* __restrict__ bu,
                      float* __restrict__ out,
                      int ntok)
{
    extern __shared__ __align__(16) char smem[];
    ulonglong2* stg  = (ulonglong2*)(smem + OFF_STG);
    ulonglong2* pLdT = (ulonglong2*)(smem + OFF_PLD);
    float2*     pRLT = (float2*)(smem + OFF_PRL);
    ulonglong2* RuC  = (ulonglong2*)(smem + OFF_RUC);
    ulonglong2* BuC  = (ulonglong2*)(smem + OFF_BUC);
    float*      sRd  = (float*)(smem + OFF_RRD);
    float*      sRu  = (float*)(smem + OFF_RRU);

    const int tid = threadIdx.x;
    const ulonglong2* Ld2 = (const ulonglong2*)Ld;
    const ulonglong2* Ru2 = (const ulonglong2*)Ru;
    const ulonglong2* bu2 = (const ulonglong2*)bu;

    // k-innermost weight repack: [(i*6+j)*8 + k] <- W4[i*48 + 6k + j]
    for (int idx = tid; idx < 192; idx += NT) {
        int i = idx / 48, q = idx % 48, kk = q / 6, j = q % 6;
        int dst = (i*6 + j)*8 + kk;
        pLdT[dst] = Ld2[idx];
        pRLT[dst] = make_float2(Rd[idx], Lu[idx]);
    }
    // lane-replicated output tables: RuC[(i*6+j)*32 + l] = Ru4[i*48+(l+32j)%48]
    for (int idx = tid; idx < 768; idx += NT) {
        int i = idx / 192, r = idx % 192, j = r / 32, ll = r % 32;
        RuC[idx] = Ru2[i*48 + (ll + 32*j) % 48];
    }
    for (int idx = tid; idx < 192; idx += NT)
        BuC[idx] = bu2[(idx % 32) + 32*(idx / 32)];   // BuC[j*32+l] = bu4[l+32j]
    for (int idx = tid; idx < 64; idx += NT) {
        sRd[idx] = rule_d[idx];
        sRu[idx] = rule_u[idx];
    }
    __syncthreads();

    const int l = tid & 31;
    const int w = tid >> 5;
    const int g = l >> 3;        // group: a on input side, c on z side
    const int k = l & 7;

    float biasD[6];
#pragma unroll
    for (int j = 0; j < 6; j++)
        biasD[j] = bd[6*l + j];

    int wsl[6], rsl[6];
#pragma unroll
    for (int j = 0; j < 6; j++) {
        wsl[j] = SW(l + 32*j);   // coalesced stage side
        rsl[j] = SW(6*l + j);    // transposed stage side
    }

    const ulonglong2* x2 = (const ulonglong2*)x;
    ulonglong2*       o2 = (ulonglong2*)out;
    ulonglong2* stgW = stg + (size_t)w * (TPI * 192);

    const int gwarp = blockIdx.x * NW + w;
    const int nwarp = gridDim.x * NW;

    for (int base = gwarp * TPI; base < ntok; base += nwarp * TPI) {
        // ---- stage in: TPI tokens, coalesced LDG.128 -> swizzled STS ----
        __syncwarp();   // prior iteration's stage reads complete
#pragma unroll
        for (int tt = 0; tt < TPI; tt++) {
            int t = base + tt; if (t > ntok - 1) t = ntok - 1;
            const ulonglong2* xr = x2 + (size_t)t * 192;
#pragma unroll
            for (int j = 0; j < 6; j++)
                stgW[tt*192 + wsl[j]] = xr[l + 32*j];
        }
        __syncwarp();

        // ---- down stage 1: si partials (1-wf broadcast weights) ----
        u64 si2[TPI][4];
#pragma unroll
        for (int tt = 0; tt < TPI; tt++)
#pragma unroll
            for (int i = 0; i < 4; i++) si2[tt][i] = 0ull;

#pragma unroll
        for (int j = 0; j < 6; j++) {
            ulonglong2 u[TPI];
#pragma unroll
            for (int tt = 0; tt < TPI; tt++)
                u[tt] = stgW[tt*192 + rsl[j]];
#pragma unroll
            for (int i = 0; i < 4; i++) {
                ulonglong2 wv = pLdT[(i*6 + j)*8 + k];
#pragma unroll
                for (int tt = 0; tt < TPI; tt++) {
                    si2[tt][i] = fma2(u[tt].x, wv.x, si2[tt][i]);
                    si2[tt][i] = fma2(u[tt].y, wv.y, si2[tt][i]);
                }
            }
        }
        float si[TPI][4];
#pragma unroll
        for (int tt = 0; tt < TPI; tt++)
#pragma unroll
            for (int i = 0; i < 4; i++) {
                float v = sum2(si2[tt][i]);
                v += __shfl_xor_sync(0xffffffffu, v, 4);
                v += __shfl_xor_sync(0xffffffffu, v, 2);
                v += __shfl_xor_sync(0xffffffffu, v, 1);
                si[tt][i] = v;
            }

        // ---- down stage 2: t[c][i] (c = g) ----
        float tD[TPI][4];
#pragma unroll
        for (int tt = 0; tt < TPI; tt++)
#pragma unroll
            for (int i = 0; i < 4; i++) tD[tt][i] = 0.f;
#pragma unroll
        for (int a = 0; a < 4; a++)
#pragma unroll
            for (int i = 0; i < 4; i++) {
                float r = sRd[i*16 + a*4 + g];
#pragma unroll
                for (int tt = 0; tt < TPI; tt++)
                    tD[tt][i] = fmaf(r, __shfl_sync(0xffffffffu, si[tt][i], a*8 + k),
                                     tD[tt][i]);
            }

        // ---- fused z -> gelu_new -> up stage 1 (s2) ----
        float s2[TPI][4];
#pragma unroll
        for (int tt = 0; tt < TPI; tt++)
#pragma unroll
            for (int i = 0; i < 4; i++) s2[tt][i] = 0.f;

#pragma unroll
        for (int j = 0; j < 6; j++) {
            float2 rl[4];
#pragma unroll
            for (int i = 0; i < 4; i++) rl[i] = pRLT[(i*6 + j)*8 + k];
            float zv[TPI];
#pragma unroll
            for (int tt = 0; tt < TPI; tt++) zv[tt] = biasD[j];
#pragma unroll
            for (int i = 0; i < 4; i++)
#pragma unroll
                for (int tt = 0; tt < TPI; tt++)
                    zv[tt] = fmaf(tD[tt][i], rl[i].x, zv[tt]);
#pragma unroll
            for (int tt = 0; tt < TPI; tt++) {
                float z   = zv[tt];
                float arg = 0.7978845608028654f * fmaf(0.044715f*z, z*z, z);
                float h   = 0.5f * z;
                zv[tt] = fmaf(h, tanh_fast(arg), h);   // 0.5z(1+tanh)
            }
#pragma unroll
            for (int i = 0; i < 4; i++)
#pragma unroll
                for (int tt = 0; tt < TPI; tt++)
                    s2[tt][i] = fmaf(zv[tt], rl[i].y, s2[tt][i]);
        }
#pragma unroll
        for (int tt = 0; tt < TPI; tt++)
#pragma unroll
            for (int i = 0; i < 4; i++) {
                float v = s2[tt][i];
                v += __shfl_xor_sync(0xffffffffu, v, 4);
                v += __shfl_xor_sync(0xffffffffu, v, 2);
                v += __shfl_xor_sync(0xffffffffu, v, 1);
                s2[tt][i] = v;
            }

        // ---- up stage 2: tU[c][i] (c = g); group-uniform ----
        float tU[TPI][4];
#pragma unroll
        for (int tt = 0; tt < TPI; tt++)
#pragma unroll
            for (int i = 0; i < 4; i++) {
                float acc = 0.f;
#pragma unroll
                for (int a = 0; a < 4; a++)
                    acc = fmaf(sRu[i*16 + a*4 + g],
                               __shfl_sync(0xffffffffu, s2[tt][i], a*8 + k), acc);
                tU[tt][i] = acc;
            }

        // ---- direct coalesced output: f = l + 32j; tU via 1 SHFL ----
#pragma unroll
        for (int j = 0; j < 6; j++) {
            ulonglong2 rv[4];
#pragma unroll
            for (int i = 0; i < 4; i++) rv[i] = RuC[(i*6 + j)*32 + l];
            ulonglong2 bb = BuC[j*32 + l];
            const int src = ((l + 32*j) / 48) * 8 + k;
#pragma unroll
            for (int tt = 0; tt < TPI; tt++) {
                ulonglong2 o = bb;
#pragma unroll
                for (int i = 0; i < 4; i++) {
                    float tv = __shfl_sync(0xffffffffu, tU[tt][i], src);
                    u64 tvp = pk2(tv, tv);
                    o.x = fma2(tvp, rv[i].x, o.x);
                    o.y = fma2(tvp, rv[i].y, o.y);
                }
                if (base + tt < ntok)
                    o2[(size_t)(base + tt) * 192 + l + 32*j] = o;
            }
        }
    }
}

extern "C" void kernel_launch(void* const* d_in, const int* in_sizes, int n_in,
                              void* d_out, int out_size)
{
    const float* x      = (const float*)d_in[0];
    const float* rule_d = (const float*)d_in[1];
    const float* Ld     = (const float*)d_in[2];
    const float* Rd     = (const float*)d_in[3];
    const float* bd     = (const float*)d_in[4];
    const float* rule_u = (const float*)d_in[5];
    const float* Lu     = (const float*)d_in[6];
    const float* Ru     = (const float*)d_in[7];
    const float* bu     = (const float*)d_in[8];

    const int ntok = in_sizes[0] / 768;

    cudaFuncSetAttribute(phm_fused_kernel,
                         cudaFuncAttributeMaxDynamicSharedMemorySize,
                         SMEM_TOTAL);

    // 148 SMs * 5 CTAs (128 thr, 44KB smem each) = one full wave
    phm_fused_kernel<<<740, NT, SMEM_TOTAL>>>(x, rule_d, Ld, Rd, bd,
                                              rule_u, Lu, Ru, bu,
                                              (float*)d_out, ntok);
}

// round 11
// speedup vs baseline: 1.0298x; 1.0298x over previous
#include <cuda_runtime.h>

// HyperComplexAdapterBlock: y = phm_up(gelu_new(phm_down(x))), rank-1 PHM.
// R11 = R6 dataflow (best so far: staged-coalesced I/O both directions,
// transposed-output compute, f32x2, tanh.approx) with latency-oriented
// tuning: TPI=2 shrinks smem to 32.8KB -> 6 CTAs/SM (24 warps, was 20),
// and down2/up2 use group-uniform shfl_xor weighted rotation (3 SHFL per
// accumulator instead of 4). Direct-global variants (R5/R7/R8) and
// direct-out variants (R3/R10) all lost to this structure.

typedef unsigned long long u64;

__device__ __forceinline__ u64 fma2(u64 a, u64 b, u64 c) {
    u64 d;
    asm("fma.rn.f32x2 %0, %1, %2, %3;" : "=l"(d) : "l"(a), "l"(b), "l"(c));
    return d;
}
__device__ __forceinline__ u64 add2(u64 a, u64 b) {
    u64 d;
    asm("add.rn.f32x2 %0, %1, %2;" : "=l"(d) : "l"(a), "l"(b));
    return d;
}
__device__ __forceinline__ u64 pk2(float lo, float hi) {
    u64 r; asm("mov.b64 %0, {%1, %2};" : "=l"(r) : "f"(lo), "f"(hi));
    return r;
}
__device__ __forceinline__ float sum2(u64 v) {
    float a, b; asm("mov.b64 {%0, %1}, %2;" : "=f"(a), "=f"(b) : "l"(v));
    return a + b;
}
__device__ __forceinline__ float tanh_fast(float x) {
    float y; asm("tanh.approx.f32 %0, %1;" : "=f"(y) : "f"(x));
    return y;
}

#define NW 4          // warps per CTA
#define NT 128        // threads per CTA
#define TPI 2         // tokens per warp-iteration
#define CPB 6         // CTAs per SM
#define SW(f) ((f) ^ (((f) >> 3) & 1))

// dynamic smem layout (bytes)
#define OFF_STG   0
#define SZ_STG    (NW * TPI * 192 * 16)           // 24576
#define OFF_PLD   (OFF_STG + SZ_STG)              // 192 f4 k-innermost
#define OFF_PRU   (OFF_PLD + 3072)                // 192 f4 k-innermost
#define OFF_PRL   (OFF_PRU + 3072)                // 192 float2 (Rd,Lu) k-inner
#define OFF_RRD   (OFF_PRL + 1536)                // 64 f rule_d
#define OFF_RRU   (OFF_RRD + 256)                 // 64 f rule_u
#define SMEM_TOTAL (OFF_RRU + 256)                // 32768

__global__ __launch_bounds__(NT, CPB)
void phm_fused_kernel(const float* __restrict__ x,
                      const float* __restrict__ rule_d,
                      const float* __restrict__ Ld,
                      const float* __restrict__ Rd,
                      const float* __restrict__ bd,
                      const float* __restrict__ rule_u,
                      const float* __restrict__ Lu,
                      const float* __restrict__ Ru,
                      const float* __restrict__ bu,
                      float* __restrict__ out,
                      int ntok)
{
    extern __shared__ __align__(16) char smem[];
    ulonglong2* stg  = (ulonglong2*)(smem + OFF_STG);
    ulonglong2* pLdT = (ulonglong2*)(smem + OFF_PLD);
    ulonglong2* pRuT = (ulonglong2*)(smem + OFF_PRU);
    float2*     pRLT = (float2*)(smem + OFF_PRL);
    float*      sRd  = (float*)(smem + OFF_RRD);
    float*      sRu  = (float*)(smem + OFF_RRU);

    const int tid = threadIdx.x;
    const ulonglong2* Ld2 = (const ulonglong2*)Ld;
    const ulonglong2* Ru2 = (const ulonglong2*)Ru;
    const ulonglong2* bu2 = (const ulonglong2*)bu;

    // k-innermost repack: table[(i*6 + j)*8 + k] <- W4[i*48 + 6k + j]
    for (int idx = tid; idx < 192; idx += NT) {
        int i = idx / 48, q = idx % 48, kk = q / 6, j = q % 6;
        int dst = (i*6 + j)*8 + kk;
        pLdT[dst] = Ld2[idx];
        pRuT[dst] = Ru2[idx];
        pRLT[dst] = make_float2(Rd[idx], Lu[idx]);
    }
    for (int idx = tid; idx < 64; idx += NT) {
        sRd[idx] = rule_d[idx];
        sRu[idx] = rule_u[idx];
    }
    __syncthreads();

    const int l = tid & 31;
    const int w = tid >> 5;
    const int g = l >> 3;        // group: a on input side, c on z/output side
    const int k = l & 7;

    float biasD[6];
#pragma unroll
    for (int j = 0; j < 6; j++)
        biasD[j] = bd[6*l + j];

    int wsl[6], rsl[6];
#pragma unroll
    for (int j = 0; j < 6; j++) {
        wsl[j] = SW(l + 32*j);   // coalesced stage side
        rsl[j] = SW(6*l + j);    // transposed stage side
    }

    const ulonglong2* x2 = (const ulonglong2*)x;
    ulonglong2*       o2 = (ulonglong2*)out;
    ulonglong2* stgW = stg + (size_t)w * (TPI * 192);

    const int gwarp = blockIdx.x * NW + w;
    const int nwarp = gridDim.x * NW;

    for (int base = gwarp * TPI; base < ntok; base += nwarp * TPI) {
        // ---- stage in: TPI tokens, coalesced LDG.128 -> swizzled STS ----
        __syncwarp();   // prior out-stage reads complete before overwrite
#pragma unroll
        for (int tt = 0; tt < TPI; tt++) {
            int t = base + tt; if (t > ntok - 1) t = ntok - 1;
            const ulonglong2* xr = x2 + (size_t)t * 192;
#pragma unroll
            for (int j = 0; j < 6; j++)
                stgW[tt*192 + wsl[j]] = xr[l + 32*j];
        }
        __syncwarp();

        // ---- down stage 1: si partials (broadcast weights) ----
        u64 si2[TPI][4];
#pragma unroll
        for (int tt = 0; tt < TPI; tt++)
#pragma unroll
            for (int i = 0; i < 4; i++) si2[tt][i] = 0ull;

#pragma unroll
        for (int j = 0; j < 6; j++) {
            ulonglong2 u[TPI];
#pragma unroll
            for (int tt = 0; tt < TPI; tt++)
                u[tt] = stgW[tt*192 + rsl[j]];
#pragma unroll
            for (int i = 0; i < 4; i++) {
                ulonglong2 wv = pLdT[(i*6 + j)*8 + k];
#pragma unroll
                for (int tt = 0; tt < TPI; tt++) {
                    si2[tt][i] = fma2(u[tt].x, wv.x, si2[tt][i]);
                    si2[tt][i] = fma2(u[tt].y, wv.y, si2[tt][i]);
                }
            }
        }
        // butterfly within 8-lane groups -> group-uniform si
        float si[TPI][4];
#pragma unroll
        for (int tt = 0; tt < TPI; tt++)
#pragma unroll
            for (int i = 0; i < 4; i++) {
                float v = sum2(si2[tt][i]);
                v += __shfl_xor_sync(0xffffffffu, v, 4);
                v += __shfl_xor_sync(0xffffffffu, v, 2);
                v += __shfl_xor_sync(0xffffffffu, v, 1);
                si[tt][i] = v;
            }

        // ---- down stage 2: weighted rotate (3 SHFL per i per tt) ----
        // tD[c=g][i] = sum_m rule_d[i, a=g^m, c=g] * s[g^m][i]
        float tD[TPI][4];
#pragma unroll
        for (int tt = 0; tt < TPI; tt++)
#pragma unroll
            for (int i = 0; i < 4; i++)
                tD[tt][i] = sRd[i*16 + 5*g] * si[tt][i];
#pragma unroll
        for (int m = 1; m < 4; m++)
#pragma unroll
            for (int i = 0; i < 4; i++) {
                float r = sRd[i*16 + ((g ^ m) << 2) + g];
#pragma unroll
                for (int tt = 0; tt < TPI; tt++)
                    tD[tt][i] = fmaf(r, __shfl_xor_sync(0xffffffffu, si[tt][i], m*8),
                                     tD[tt][i]);
            }

        // ---- fused z -> gelu_new -> up stage 1 (s2) ----
        float s2[TPI][4];
#pragma unroll
        for (int tt = 0; tt < TPI; tt++)
#pragma unroll
            for (int i = 0; i < 4; i++) s2[tt][i] = 0.f;

#pragma unroll
        for (int j = 0; j < 6; j++) {
            float2 rl[4];
#pragma unroll
            for (int i = 0; i < 4; i++) rl[i] = pRLT[(i*6 + j)*8 + k];
            float zv[TPI];
#pragma unroll
            for (int tt = 0; tt < TPI; tt++) zv[tt] = biasD[j];
#pragma unroll
            for (int i = 0; i < 4; i++)
#pragma unroll
                for (int tt = 0; tt < TPI; tt++)
                    zv[tt] = fmaf(tD[tt][i], rl[i].x, zv[tt]);
#pragma unroll
            for (int tt = 0; tt < TPI; tt++) {
                float z   = zv[tt];
                float arg = 0.7978845608028654f * fmaf(0.044715f*z, z*z, z);
                float h   = 0.5f * z;
                zv[tt] = fmaf(h, tanh_fast(arg), h);   // 0.5z(1+tanh)
            }
#pragma unroll
            for (int i = 0; i < 4; i++)
#pragma unroll
                for (int tt = 0; tt < TPI; tt++)
                    s2[tt][i] = fmaf(zv[tt], rl[i].y, s2[tt][i]);
        }
        // butterfly -> group-uniform s2
#pragma unroll
        for (int tt = 0; tt < TPI; tt++)
#pragma unroll
            for (int i = 0; i < 4; i++) {
                float v = s2[tt][i];
                v += __shfl_xor_sync(0xffffffffu, v, 4);
                v += __shfl_xor_sync(0xffffffffu, v, 2);
                v += __shfl_xor_sync(0xffffffffu, v, 1);
                s2[tt][i] = v;
            }

        // ---- up stage 2: weighted rotate, packed for output ----
        float tU[TPI][4];
#pragma unroll
        for (int tt = 0; tt < TPI; tt++)
#pragma unroll
            for (int i = 0; i < 4; i++)
                tU[tt][i] = sRu[i*16 + 5*g] * s2[tt][i];
#pragma unroll
        for (int m = 1; m < 4; m++)
#pragma unroll
            for (int i = 0; i < 4; i++) {
                float r = sRu[i*16 + ((g ^ m) << 2) + g];
#pragma unroll
                for (int tt = 0; tt < TPI; tt++)
                    tU[tt][i] = fmaf(r, __shfl_xor_sync(0xffffffffu, s2[tt][i], m*8),
                                     tU[tt][i]);
            }
        u64 tUp[TPI][4];
#pragma unroll
        for (int tt = 0; tt < TPI; tt++)
#pragma unroll
            for (int i = 0; i < 4; i++)
                tUp[tt][i] = pk2(tU[tt][i], tU[tt][i]);

        // ---- output: transposed compute -> swizzled STS -> coalesced
        //      LDS + bias + STG ----
        __syncwarp();   // x-stage reads complete before overwrite
#pragma unroll
        for (int j = 0; j < 6; j++) {
            ulonglong2 rv[4];
#pragma unroll
            for (int i = 0; i < 4; i++) rv[i] = pRuT[(i*6 + j)*8 + k];
#pragma unroll
            for (int tt = 0; tt < TPI; tt++) {
                ulonglong2 o; o.x = 0ull; o.y = 0ull;
#pragma unroll
                for (int i = 0; i < 4; i++) {
                    o.x = fma2(tUp[tt][i], rv[i].x, o.x);
                    o.y = fma2(tUp[tt][i], rv[i].y, o.y);
                }
                stgW[tt*192 + rsl[j]] = o;
            }
        }
        __syncwarp();
#pragma unroll
        for (int j = 0; j < 6; j++) {
            ulonglong2 bb = __ldg(&bu2[l + 32*j]);   // L1-resident after iter 1
#pragma unroll
            for (int tt = 0; tt < TPI; tt++) {
                if (base + tt < ntok) {
                    ulonglong2 v = stgW[tt*192 + wsl[j]];
                    v.x = add2(v.x, bb.x);
                    v.y = add2(v.y, bb.y);
                    o2[(size_t)(base + tt) * 192 + l + 32*j] = v;
                }
            }
        }
    }
}

extern "C" void kernel_launch(void* const* d_in, const int* in_sizes, int n_in,
                              void* d_out, int out_size)
{
    const float* x      = (const float*)d_in[0];
    const float* rule_d = (const float*)d_in[1];
    const float* Ld     = (const float*)d_in[2];
    const float* Rd     = (const float*)d_in[3];
    const float* bd     = (const float*)d_in[4];
    const float* rule_u = (const float*)d_in[5];
    const float* Lu     = (const float*)d_in[6];
    const float* Ru     = (const float*)d_in[7];
    const float* bu     = (const float*)d_in[8];

    const int ntok = in_sizes[0] / 768;

    cudaFuncSetAttribute(phm_fused_kernel,
                         cudaFuncAttributeMaxDynamicSharedMemorySize,
                         SMEM_TOTAL);

    // 148 SMs * 6 CTAs (128 thr, 32.8KB smem each) = one full wave
    phm_fused_kernel<<<148 * CPB, NT, SMEM_TOTAL>>>(x, rule_d, Ld, Rd, bd,
                                                    rule_u, Lu, Ru, bu,
                                                    (float*)d_out, ntok);
}

// round 12
// speedup vs baseline: 1.0807x; 1.0494x over previous
#include <cuda_runtime.h>

// HyperComplexAdapterBlock: y = phm_up(gelu_new(phm_down(x))), rank-1 PHM.
// R12 = R6 (champion) with the INPUT stage deleted: lane (g=l/8, k=l%8)
// loads x granules {48g + k + 8m} directly from gmem — lanes k=0..7 of each
// group cover one contiguous 128B line per instruction (sector-exact, each
// line read once per warp), so no transpose stage is needed on the way in
// (-48 L1 wf/token). Output keeps the R6 path (transposed compute ->
// swizzled smem stage -> coalesced STG): R5 proved direct strided STG
// triggers L2 read-modify-write (+75% DRAM). Plus R11's weighted-rotate
// shuffle reduction (48 SHFL/token vs 56). TPI=3, 5 CTAs/SM.

typedef unsigned long long u64;

__device__ __forceinline__ u64 fma2(u64 a, u64 b, u64 c) {
    u64 d;
    asm("fma.rn.f32x2 %0, %1, %2, %3;" : "=l"(d) : "l"(a), "l"(b), "l"(c));
    return d;
}
__device__ __forceinline__ u64 add2(u64 a, u64 b) {
    u64 d;
    asm("add.rn.f32x2 %0, %1, %2;" : "=l"(d) : "l"(a), "l"(b));
    return d;
}
__device__ __forceinline__ u64 pk2(float lo, float hi) {
    u64 r; asm("mov.b64 %0, {%1, %2};" : "=l"(r) : "f"(lo), "f"(hi));
    return r;
}
__device__ __forceinline__ float sum2(u64 v) {
    float a, b; asm("mov.b64 {%0, %1}, %2;" : "=f"(a), "=f"(b) : "l"(v));
    return a + b;
}
__device__ __forceinline__ float tanh_fast(float x) {
    float y; asm("tanh.approx.f32 %0, %1;" : "=f"(y) : "f"(x));
    return y;
}

#define NW 4          // warps per CTA
#define NT 128        // threads per CTA
#define TPI 3         // tokens per warp-iteration
#define SW(f) ((f) ^ (((f) >> 3) & 1))

// dynamic smem layout (bytes) — stage used for OUTPUT transpose only
#define OFF_STG   0
#define SZ_STG    (NW * TPI * 192 * 16)           // 36864
#define OFF_PLD   (OFF_STG + SZ_STG)              // 192 f4, (i*6+m)*8+k keyed
#define OFF_PRU   (OFF_PLD + 3072)                // 192 f4, (i*6+j)*8+k keyed
#define OFF_PRL   (OFF_PRU + 3072)                // 192 float2 (Rd,Lu)
#define OFF_RRD   (OFF_PRL + 1536)                // 64 f rule_d
#define OFF_RRU   (OFF_RRD + 256)                 // 64 f rule_u
#define SMEM_TOTAL (OFF_RRU + 256)                // 45056

__global__ __launch_bounds__(NT, 5)
void phm_fused_kernel(const float* __restrict__ x,
                      const float* __restrict__ rule_d,
                      const float* __restrict__ Ld,
                      const float* __restrict__ Rd,
                      const float* __restrict__ bd,
                      const float* __restrict__ rule_u,
                      const float* __restrict__ Lu,
                      const float* __restrict__ Ru,
                      const float* __restrict__ bu,
                      float* __restrict__ out,
                      int ntok)
{
    extern __shared__ __align__(16) char smem[];
    ulonglong2* stg  = (ulonglong2*)(smem + OFF_STG);
    ulonglong2* pLdT = (ulonglong2*)(smem + OFF_PLD);
    ulonglong2* pRuT = (ulonglong2*)(smem + OFF_PRU);
    float2*     pRLT = (float2*)(smem + OFF_PRL);
    float*      sRd  = (float*)(smem + OFF_RRD);
    float*      sRu  = (float*)(smem + OFF_RRU);

    const int tid = threadIdx.x;
    const ulonglong2* Ld2 = (const ulonglong2*)Ld;
    const ulonglong2* Ru2 = (const ulonglong2*)Ru;
    const ulonglong2* bu2 = (const ulonglong2*)bu;

    for (int idx = tid; idx < 192; idx += NT) {
        int i = idx / 48, q = idx % 48;
        // input-side table keyed by (m = q/8, k = q%8): granule q = k + 8m
        pLdT[(i*6 + (q >> 3))*8 + (q & 7)] = Ld2[idx];
        // z-side tables keyed by (k = q/6, j = q%6): scalar q = 6k + j
        int dst = (i*6 + (q % 6))*8 + (q / 6);
        pRuT[dst] = Ru2[idx];
        pRLT[dst] = make_float2(Rd[idx], Lu[idx]);
    }
    for (int idx = tid; idx < 64; idx += NT) {
        sRd[idx] = rule_d[idx];
        sRu[idx] = rule_u[idx];
    }
    __syncthreads();

    const int l = tid & 31;
    const int w = tid >> 5;
    const int g = l >> 3;        // group: a on input side, c on z/output side
    const int k = l & 7;

    float biasD[6];
#pragma unroll
    for (int j = 0; j < 6; j++)
        biasD[j] = bd[6*l + j];

    int wsl[6], rsl[6];
#pragma unroll
    for (int j = 0; j < 6; j++) {
        wsl[j] = SW(l + 32*j);   // coalesced stage side (out)
        rsl[j] = SW(6*l + j);    // transposed stage side (out)
    }

    const ulonglong2* x2 = (const ulonglong2*)x;
    ulonglong2*       o2 = (ulonglong2*)out;
    ulonglong2* stgW = stg + (size_t)w * (TPI * 192);

    const int gwarp = blockIdx.x * NW + w;
    const int nwarp = gridDim.x * NW;
    const int fbase = 48*g + k;  // lane's input-granule base in a token row

    for (int base = gwarp * TPI; base < ntok; base += nwarp * TPI) {
        size_t row[TPI];
#pragma unroll
        for (int tt = 0; tt < TPI; tt++) {
            int t = base + tt; if (t > ntok - 1) t = ntok - 1;
            row[tt] = (size_t)t * 192 + fbase;
        }

        // ---- down stage 1: direct stride-8 loads (each LDG = 4 full
        //      contiguous 128B lines across the warp) + packed FMA ----
        u64 si2[TPI][4];
#pragma unroll
        for (int tt = 0; tt < TPI; tt++)
#pragma unroll
            for (int i = 0; i < 4; i++) si2[tt][i] = 0ull;

#pragma unroll
        for (int m = 0; m < 6; m++) {
            ulonglong2 u[TPI];
#pragma unroll
            for (int tt = 0; tt < TPI; tt++)
                u[tt] = x2[row[tt] + 8*m];
#pragma unroll
            for (int i = 0; i < 4; i++) {
                ulonglong2 wv = pLdT[(i*6 + m)*8 + k];   // 1-wf broadcast
#pragma unroll
                for (int tt = 0; tt < TPI; tt++) {
                    si2[tt][i] = fma2(u[tt].x, wv.x, si2[tt][i]);
                    si2[tt][i] = fma2(u[tt].y, wv.y, si2[tt][i]);
                }
            }
        }
        // butterfly within 8-lane groups -> group-uniform si
        float si[TPI][4];
#pragma unroll
        for (int tt = 0; tt < TPI; tt++)
#pragma unroll
            for (int i = 0; i < 4; i++) {
                float v = sum2(si2[tt][i]);
                v += __shfl_xor_sync(0xffffffffu, v, 4);
                v += __shfl_xor_sync(0xffffffffu, v, 2);
                v += __shfl_xor_sync(0xffffffffu, v, 1);
                si[tt][i] = v;
            }

        // ---- down stage 2: weighted rotate (3 SHFL per i) ----
        float tD[TPI][4];
#pragma unroll
        for (int tt = 0; tt < TPI; tt++)
#pragma unroll
            for (int i = 0; i < 4; i++)
                tD[tt][i] = sRd[i*16 + 5*g] * si[tt][i];
#pragma unroll
        for (int m = 1; m < 4; m++)
#pragma unroll
            for (int i = 0; i < 4; i++) {
                float r = sRd[i*16 + ((g ^ m) << 2) + g];
#pragma unroll
                for (int tt = 0; tt < TPI; tt++)
                    tD[tt][i] = fmaf(r, __shfl_xor_sync(0xffffffffu, si[tt][i], m*8),
                                     tD[tt][i]);
            }

        // ---- fused z -> gelu_new -> up stage 1 (s2); lane z: q = 6k+j ----
        float s2[TPI][4];
#pragma unroll
        for (int tt = 0; tt < TPI; tt++)
#pragma unroll
            for (int i = 0; i < 4; i++) s2[tt][i] = 0.f;

#pragma unroll
        for (int j = 0; j < 6; j++) {
            float2 rl[4];
#pragma unroll
            for (int i = 0; i < 4; i++) rl[i] = pRLT[(i*6 + j)*8 + k];
            float zv[TPI];
#pragma unroll
            for (int tt = 0; tt < TPI; tt++) zv[tt] = biasD[j];
#pragma unroll
            for (int i = 0; i < 4; i++)
#pragma unroll
                for (int tt = 0; tt < TPI; tt++)
                    zv[tt] = fmaf(tD[tt][i], rl[i].x, zv[tt]);
#pragma unroll
            for (int tt = 0; tt < TPI; tt++) {
                float z   = zv[tt];
                float arg = 0.7978845608028654f * fmaf(0.044715f*z, z*z, z);
                float h   = 0.5f * z;
                zv[tt] = fmaf(h, tanh_fast(arg), h);   // 0.5z(1+tanh)
            }
#pragma unroll
            for (int i = 0; i < 4; i++)
#pragma unroll
                for (int tt = 0; tt < TPI; tt++)
                    s2[tt][i] = fmaf(zv[tt], rl[i].y, s2[tt][i]);
        }
        // butterfly -> group-uniform s2
#pragma unroll
        for (int tt = 0; tt < TPI; tt++)
#pragma unroll
            for (int i = 0; i < 4; i++) {
                float v = s2[tt][i];
                v += __shfl_xor_sync(0xffffffffu, v, 4);
                v += __shfl_xor_sync(0xffffffffu, v, 2);
                v += __shfl_xor_sync(0xffffffffu, v, 1);
                s2[tt][i] = v;
            }

        // ---- up stage 2: weighted rotate, packed ----
        float tU[TPI][4];
#pragma unroll
        for (int tt = 0; tt < TPI; tt++)
#pragma unroll
            for (int i = 0; i < 4; i++)
                tU[tt][i] = sRu[i*16 + 5*g] * s2[tt][i];
#pragma unroll
        for (int m = 1; m < 4; m++)
#pragma unroll
            for (int i = 0; i < 4; i++) {
                float r = sRu[i*16 + ((g ^ m) << 2) + g];
#pragma unroll
                for (int tt = 0; tt < TPI; tt++)
                    tU[tt][i] = fmaf(r, __shfl_xor_sync(0xffffffffu, s2[tt][i], m*8),
                                     tU[tt][i]);
            }
        u64 tUp[TPI][4];
#pragma unroll
        for (int tt = 0; tt < TPI; tt++)
#pragma unroll
            for (int i = 0; i < 4; i++)
                tUp[tt][i] = pk2(tU[tt][i], tU[tt][i]);

        // ---- output: transposed compute -> swizzled STS -> coalesced
        //      LDS + bias + STG ----
        __syncwarp();   // prior iteration's coalesced reads complete
#pragma unroll
        for (int j = 0; j < 6; j++) {
            ulonglong2 rv[4];
#pragma unroll
            for (int i = 0; i < 4; i++) rv[i] = pRuT[(i*6 + j)*8 + k];
#pragma unroll
            for (int tt = 0; tt < TPI; tt++) {
                ulonglong2 o; o.x = 0ull; o.y = 0ull;
#pragma unroll
                for (int i = 0; i < 4; i++) {
                    o.x = fma2(tUp[tt][i], rv[i].x, o.x);
                    o.y = fma2(tUp[tt][i], rv[i].y, o.y);
                }
                stgW[tt*192 + rsl[j]] = o;
            }
        }
        __syncwarp();
#pragma unroll
        for (int j = 0; j < 6; j++) {
            ulonglong2 bb = __ldg(&bu2[l + 32*j]);   // L1-resident after iter 1
#pragma unroll
            for (int tt = 0; tt < TPI; tt++) {
                if (base + tt < ntok) {
                    ulonglong2 v = stgW[tt*192 + wsl[j]];
                    v.x = add2(v.x, bb.x);
                    v.y = add2(v.y, bb.y);
                    o2[(size_t)(base + tt) * 192 + l + 32*j] = v;
                }
            }
        }
    }
}

extern "C" void kernel_launch(void* const* d_in, const int* in_sizes, int n_in,
                              void* d_out, int out_size)
{
    const float* x      = (const float*)d_in[0];
    const float* rule_d = (const float*)d_in[1];
    const float* Ld     = (const float*)d_in[2];
    const float* Rd     = (const float*)d_in[3];
    const float* bd     = (const float*)d_in[4];
    const float* rule_u = (const float*)d_in[5];
    const float* Lu     = (const float*)d_in[6];
    const float* Ru     = (const float*)d_in[7];
    const float* bu     = (const float*)d_in[8];

    const int ntok = in_sizes[0] / 768;

    cudaFuncSetAttribute(phm_fused_kernel,
                         cudaFuncAttributeMaxDynamicSharedMemorySize,
                         SMEM_TOTAL);

    // 148 SMs * 5 CTAs (128 thr, 44KB smem each) = one full wave
    phm_fused_kernel<<<740, NT, SMEM_TOTAL>>>(x, rule_d, Ld, Rd, bd,
                                              rule_u, Lu, Ru, bu,
                                              (float*)d_out, ntok);
}

// round 13
// speedup vs baseline: 1.0852x; 1.0042x over previous
#include <cuda_runtime.h>

// HyperComplexAdapterBlock: y = phm_up(gelu_new(phm_down(x))), rank-1 PHM.
// R13 = R12 (champion: direct stride-8 coalesced-by-line input loads, no
// input stage; transposed-output compute -> swizzled smem stage ->
// coalesced STG; weighted-rotate shuffles; f32x2; tanh.approx) with:
//   * TPI=4 (weights/rules/bias amortized over 4 tokens, was 3)
//   * out-stage drained in 2-token chunks so the stage buffer is half-size
//     (24.6KB; 32.8KB total smem) -> still 5 CTAs/SM at the 102-reg budget.

typedef unsigned long long u64;

__device__ __forceinline__ u64 fma2(u64 a, u64 b, u64 c) {
    u64 d;
    asm("fma.rn.f32x2 %0, %1, %2, %3;" : "=l"(d) : "l"(a), "l"(b), "l"(c));
    return d;
}
__device__ __forceinline__ u64 add2(u64 a, u64 b) {
    u64 d;
    asm("add.rn.f32x2 %0, %1, %2;" : "=l"(d) : "l"(a), "l"(b));
    return d;
}
__device__ __forceinline__ u64 pk2(float lo, float hi) {
    u64 r; asm("mov.b64 %0, {%1, %2};" : "=l"(r) : "f"(lo), "f"(hi));
    return r;
}
__device__ __forceinline__ float sum2(u64 v) {
    float a, b; asm("mov.b64 {%0, %1}, %2;" : "=f"(a), "=f"(b) : "l"(v));
    return a + b;
}
__device__ __forceinline__ float tanh_fast(float x) {
    float y; asm("tanh.approx.f32 %0, %1;" : "=f"(y) : "f"(x));
    return y;
}

#define NW 4          // warps per CTA
#define NT 128        // threads per CTA
#define TPI 4         // tokens per warp-iteration
#define CHK 2         // tokens staged per output chunk
#define SW(f) ((f) ^ (((f) >> 3) & 1))

// dynamic smem layout (bytes) — stage holds CHK tokens per warp
#define OFF_STG   0
#define SZ_STG    (NW * CHK * 192 * 16)           // 24576
#define OFF_PLD   (OFF_STG + SZ_STG)              // 192 f4, (i*6+m)*8+k keyed
#define OFF_PRU   (OFF_PLD + 3072)                // 192 f4, (i*6+j)*8+k keyed
#define OFF_PRL   (OFF_PRU + 3072)                // 192 float2 (Rd,Lu)
#define OFF_RRD   (OFF_PRL + 1536)                // 64 f rule_d
#define OFF_RRU   (OFF_RRD + 256)                 // 64 f rule_u
#define SMEM_TOTAL (OFF_RRU + 256)                // 32768

__global__ __launch_bounds__(NT, 5)
void phm_fused_kernel(const float* __restrict__ x,
                      const float* __restrict__ rule_d,
                      const float* __restrict__ Ld,
                      const float* __restrict__ Rd,
                      const float* __restrict__ bd,
                      const float* __restrict__ rule_u,
                      const float* __restrict__ Lu,
                      const float* __restrict__ Ru,
                      const float* __restrict__ bu,
                      float* __restrict__ out,
                      int ntok)
{
    extern __shared__ __align__(16) char smem[];
    ulonglong2* stg  = (ulonglong2*)(smem + OFF_STG);
    ulonglong2* pLdT = (ulonglong2*)(smem + OFF_PLD);
    ulonglong2* pRuT = (ulonglong2*)(smem + OFF_PRU);
    float2*     pRLT = (float2*)(smem + OFF_PRL);
    float*      sRd  = (float*)(smem + OFF_RRD);
    float*      sRu  = (float*)(smem + OFF_RRU);

    const int tid = threadIdx.x;
    const ulonglong2* Ld2 = (const ulonglong2*)Ld;
    const ulonglong2* Ru2 = (const ulonglong2*)Ru;
    const ulonglong2* bu2 = (const ulonglong2*)bu;

    for (int idx = tid; idx < 192; idx += NT) {
        int i = idx / 48, q = idx % 48;
        // input-side table keyed by (m = q/8, k = q%8): granule q = k + 8m
        pLdT[(i*6 + (q >> 3))*8 + (q & 7)] = Ld2[idx];
        // z-side tables keyed by (k = q/6, j = q%6): scalar q = 6k + j
        int dst = (i*6 + (q % 6))*8 + (q / 6);
        pRuT[dst] = Ru2[idx];
        pRLT[dst] = make_float2(Rd[idx], Lu[idx]);
    }
    for (int idx = tid; idx < 64; idx += NT) {
        sRd[idx] = rule_d[idx];
        sRu[idx] = rule_u[idx];
    }
    __syncthreads();

    const int l = tid & 31;
    const int w = tid >> 5;
    const int g = l >> 3;        // group: a on input side, c on z/output side
    const int k = l & 7;

    float biasD[6];
#pragma unroll
    for (int j = 0; j < 6; j++)
        biasD[j] = bd[6*l + j];

    int wsl[6], rsl[6];
#pragma unroll
    for (int j = 0; j < 6; j++) {
        wsl[j] = SW(l + 32*j);   // coalesced stage side (out)
        rsl[j] = SW(6*l + j);    // transposed stage side (out)
    }

    const ulonglong2* x2 = (const ulonglong2*)x;
    ulonglong2*       o2 = (ulonglong2*)out;
    ulonglong2* stgW = stg + (size_t)w * (CHK * 192);

    const int gwarp = blockIdx.x * NW + w;
    const int nwarp = gridDim.x * NW;
    const int fbase = 48*g + k;  // lane's input-granule base in a token row

    for (int base = gwarp * TPI; base < ntok; base += nwarp * TPI) {
        int row[TPI];
#pragma unroll
        for (int tt = 0; tt < TPI; tt++) {
            int t = base + tt; if (t > ntok - 1) t = ntok - 1;
            row[tt] = t * 192 + fbase;
        }

        // ---- down stage 1: direct stride-8 loads (each LDG = 4 full
        //      contiguous 128B lines across the warp) + packed FMA ----
        u64 si2[TPI][4];
#pragma unroll
        for (int tt = 0; tt < TPI; tt++)
#pragma unroll
            for (int i = 0; i < 4; i++) si2[tt][i] = 0ull;

#pragma unroll
        for (int m = 0; m < 6; m++) {
            ulonglong2 u[TPI];
#pragma unroll
            for (int tt = 0; tt < TPI; tt++)
                u[tt] = x2[row[tt] + 8*m];
#pragma unroll
            for (int i = 0; i < 4; i++) {
                ulonglong2 wv = pLdT[(i*6 + m)*8 + k];   // 1-wf broadcast
#pragma unroll
                for (int tt = 0; tt < TPI; tt++) {
                    si2[tt][i] = fma2(u[tt].x, wv.x, si2[tt][i]);
                    si2[tt][i] = fma2(u[tt].y, wv.y, si2[tt][i]);
                }
            }
        }
        // butterfly within 8-lane groups -> group-uniform si
        float si[TPI][4];
#pragma unroll
        for (int tt = 0; tt < TPI; tt++)
#pragma unroll
            for (int i = 0; i < 4; i++) {
                float v = sum2(si2[tt][i]);
                v += __shfl_xor_sync(0xffffffffu, v, 4);
                v += __shfl_xor_sync(0xffffffffu, v, 2);
                v += __shfl_xor_sync(0xffffffffu, v, 1);
                si[tt][i] = v;
            }

        // ---- down stage 2: weighted rotate (3 SHFL per i) ----
        float tD[TPI][4];
#pragma unroll
        for (int tt = 0; tt < TPI; tt++)
#pragma unroll
            for (int i = 0; i < 4; i++)
                tD[tt][i] = sRd[i*16 + 5*g] * si[tt][i];
#pragma unroll
        for (int m = 1; m < 4; m++)
#pragma unroll
            for (int i = 0; i < 4; i++) {
                float r = sRd[i*16 + ((g ^ m) << 2) + g];
#pragma unroll
                for (int tt = 0; tt < TPI; tt++)
                    tD[tt][i] = fmaf(r, __shfl_xor_sync(0xffffffffu, si[tt][i], m*8),
                                     tD[tt][i]);
            }

        // ---- fused z -> gelu_new -> up stage 1 (s2); lane z: q = 6k+j ----
        float s2[TPI][4];
#pragma unroll
        for (int tt = 0; tt < TPI; tt++)
#pragma unroll
            for (int i = 0; i < 4; i++) s2[tt][i] = 0.f;

#pragma unroll
        for (int j = 0; j < 6; j++) {
            float2 rl[4];
#pragma unroll
            for (int i = 0; i < 4; i++) rl[i] = pRLT[(i*6 + j)*8 + k];
            float zv[TPI];
#pragma unroll
            for (int tt = 0; tt < TPI; tt++) zv[tt] = biasD[j];
#pragma unroll
            for (int i = 0; i < 4; i++)
#pragma unroll
                for (int tt = 0; tt < TPI; tt++)
                    zv[tt] = fmaf(tD[tt][i], rl[i].x, zv[tt]);
#pragma unroll
            for (int tt = 0; tt < TPI; tt++) {
                float z   = zv[tt];
                float arg = 0.7978845608028654f * fmaf(0.044715f*z, z*z, z);
                float h   = 0.5f * z;
                zv[tt] = fmaf(h, tanh_fast(arg), h);   // 0.5z(1+tanh)
            }
#pragma unroll
            for (int i = 0; i < 4; i++)
#pragma unroll
                for (int tt = 0; tt < TPI; tt++)
                    s2[tt][i] = fmaf(zv[tt], rl[i].y, s2[tt][i]);
        }
        // butterfly -> group-uniform s2
#pragma unroll
        for (int tt = 0; tt < TPI; tt++)
#pragma unroll
            for (int i = 0; i < 4; i++) {
                float v = s2[tt][i];
                v += __shfl_xor_sync(0xffffffffu, v, 4);
                v += __shfl_xor_sync(0xffffffffu, v, 2);
                v += __shfl_xor_sync(0xffffffffu, v, 1);
                s2[tt][i] = v;
            }

        // ---- up stage 2: weighted rotate ----
        float tU[TPI][4];
#pragma unroll
        for (int tt = 0; tt < TPI; tt++)
#pragma unroll
            for (int i = 0; i < 4; i++)
                tU[tt][i] = sRu[i*16 + 5*g] * s2[tt][i];
#pragma unroll
        for (int m = 1; m < 4; m++)
#pragma unroll
            for (int i = 0; i < 4; i++) {
                float r = sRu[i*16 + ((g ^ m) << 2) + g];
#pragma unroll
                for (int tt = 0; tt < TPI; tt++)
                    tU[tt][i] = fmaf(r, __shfl_xor_sync(0xffffffffu, s2[tt][i], m*8),
                                     tU[tt][i]);
            }

        // ---- output in 2-token chunks: transposed compute -> swizzled STS
        //      -> coalesced LDS + bias + STG ----
#pragma unroll
        for (int c0 = 0; c0 < TPI; c0 += CHK) {
            u64 tUp[CHK][4];
#pragma unroll
            for (int cc = 0; cc < CHK; cc++)
#pragma unroll
                for (int i = 0; i < 4; i++)
                    tUp[cc][i] = pk2(tU[c0+cc][i], tU[c0+cc][i]);

            __syncwarp();   // previous chunk's coalesced reads complete
#pragma unroll
            for (int j = 0; j < 6; j++) {
                ulonglong2 rv[4];
#pragma unroll
                for (int i = 0; i < 4; i++) rv[i] = pRuT[(i*6 + j)*8 + k];
#pragma unroll
                for (int cc = 0; cc < CHK; cc++) {
                    ulonglong2 o; o.x = 0ull; o.y = 0ull;
#pragma unroll
                    for (int i = 0; i < 4; i++) {
                        o.x = fma2(tUp[cc][i], rv[i].x, o.x);
                        o.y = fma2(tUp[cc][i], rv[i].y, o.y);
                    }
                    stgW[cc*192 + rsl[j]] = o;
                }
            }
            __syncwarp();
#pragma unroll
            for (int j = 0; j < 6; j++) {
                ulonglong2 bb = __ldg(&bu2[l + 32*j]);  // L1-resident
#pragma unroll
                for (int cc = 0; cc < CHK; cc++) {
                    int t = base + c0 + cc;
                    if (t < ntok) {
                        ulonglong2 v = stgW[cc*192 + wsl[j]];
                        v.x = add2(v.x, bb.x);
                        v.y = add2(v.y, bb.y);
                        o2[(size_t)t * 192 + l + 32*j] = v;
                    }
                }
            }
        }
    }
}

extern "C" void kernel_launch(void* const* d_in, const int* in_sizes, int n_in,
                              void* d_out, int out_size)
{
    const float* x      = (const float*)d_in[0];
    const float* rule_d = (const float*)d_in[1];
    const float* Ld     = (const float*)d_in[2];
    const float* Rd     = (const float*)d_in[3];
    const float* bd     = (const float*)d_in[4];
    const float* rule_u = (const float*)d_in[5];
    const float* Lu     = (const float*)d_in[6];
    const float* Ru     = (const float*)d_in[7];
    const float* bu     = (const float*)d_in[8];

    const int ntok = in_sizes[0] / 768;

    cudaFuncSetAttribute(phm_fused_kernel,
                         cudaFuncAttributeMaxDynamicSharedMemorySize,
                         SMEM_TOTAL);

    // 148 SMs * 5 CTAs (128 thr, 32.8KB smem each) = one full wave
    phm_fused_kernel<<<740, NT, SMEM_TOTAL>>>(x, rule_d, Ld, Rd, bd,
                                              rule_u, Lu, Ru, bu,
                                              (float*)d_out, ntok);
}

// round 14
// speedup vs baseline: 1.1191x; 1.0312x over previous
#include <cuda_runtime.h>
#include <cstdint>

// HyperComplexAdapterBlock: y = phm_up(gelu_new(phm_down(x))), rank-1 PHM.
// R14 = R13 front-end (direct stride-8 input LDG, weighted-rotate shuffles,
// f32x2, tanh.approx, TPI=4) + TMA-drained output: transposed compute in
// stride-8 ownership (lane (g,k) owns output granules 48g+k+8m) -> plain
// LINEAR conflict-free STS (granule%8==k) with bias folded in -> 1D
// cp.async.bulk shared->global (3072B/token) by the TMA engine. Deletes the
// warp-issued LDS+STG+bias-LDG back half (~60 wf/token of the binding L1
// pipe); gmem writes stay full-line (engine-coalesced, no RMW).

typedef unsigned long long u64;

__device__ __forceinline__ u64 fma2(u64 a, u64 b, u64 c) {
    u64 d;
    asm("fma.rn.f32x2 %0, %1, %2, %3;" : "=l"(d) : "l"(a), "l"(b), "l"(c));
    return d;
}
__device__ __forceinline__ u64 pk2(float lo, float hi) {
    u64 r; asm("mov.b64 %0, {%1, %2};" : "=l"(r) : "f"(lo), "f"(hi));
    return r;
}
__device__ __forceinline__ float sum2(u64 v) {
    float a, b; asm("mov.b64 {%0, %1}, %2;" : "=f"(a), "=f"(b) : "l"(v));
    return a + b;
}
__device__ __forceinline__ float tanh_fast(float x) {
    float y; asm("tanh.approx.f32 %0, %1;" : "=f"(y) : "f"(x));
    return y;
}
__device__ __forceinline__ void bulk_store(void* gdst, uint32_t ssrc, int bytes) {
    asm volatile("cp.async.bulk.global.shared::cta.bulk_group [%0], [%1], %2;"
                 :: "l"(gdst), "r"(ssrc), "r"(bytes) : "memory");
}

#define NW 4          // warps per CTA
#define NT 128        // threads per CTA
#define TPI 4         // tokens per warp-iteration
#define CHK 2         // tokens staged per output chunk

// dynamic smem layout (bytes)
#define OFF_STG   0
#define SZ_STG    (NW * CHK * 192 * 16)           // 24576 (linear token rows)
#define OFF_PLD   (OFF_STG + SZ_STG)              // 192 f4, (i*6+m)*8+k keyed
#define OFF_PRU   (OFF_PLD + 3072)                // 192 f4, (i*6+m)*8+k keyed
#define OFF_PRL   (OFF_PRU + 3072)                // 192 float2 (Rd,Lu), z-keyed
#define OFF_BUT   (OFF_PRL + 1536)                // 192 f4 bias_u, [m*32+l]
#define OFF_RRD   (OFF_BUT + 3072)                // 64 f rule_d
#define OFF_RRU   (OFF_RRD + 256)                 // 64 f rule_u
#define SMEM_TOTAL (OFF_RRU + 256)                // 35840

__global__ __launch_bounds__(NT, 5)
void phm_fused_kernel(const float* __restrict__ x,
                      const float* __restrict__ rule_d,
                      const float* __restrict__ Ld,
                      const float* __restrict__ Rd,
                      const float* __restrict__ bd,
                      const float* __restrict__ rule_u,
                      const float* __restrict__ Lu,
                      const float* __restrict__ Ru,
                      const float* __restrict__ bu,
                      float* __restrict__ out,
                      int ntok)
{
    extern __shared__ __align__(16) char smem[];
    ulonglong2* stg  = (ulonglong2*)(smem + OFF_STG);
    ulonglong2* pLdT = (ulonglong2*)(smem + OFF_PLD);
    ulonglong2* pRuT = (ulonglong2*)(smem + OFF_PRU);
    float2*     pRLT = (float2*)(smem + OFF_PRL);
    ulonglong2* sBuT = (ulonglong2*)(smem + OFF_BUT);
    float*      sRd  = (float*)(smem + OFF_RRD);
    float*      sRu  = (float*)(smem + OFF_RRU);

    const int tid = threadIdx.x;
    const ulonglong2* Ld2 = (const ulonglong2*)Ld;
    const ulonglong2* Ru2 = (const ulonglong2*)Ru;
    const ulonglong2* bu2 = (const ulonglong2*)bu;

    for (int idx = tid; idx < 192; idx += NT) {
        int i = idx / 48, q = idx % 48;
        // stride-8 keyed tables (m = q/8, kk = q%8): granule q = kk + 8m
        int dst8 = (i*6 + (q >> 3))*8 + (q & 7);
        pLdT[dst8] = Ld2[idx];
        pRuT[dst8] = Ru2[idx];
        // z-keyed table (kk = q/6, j = q%6): scalar q = 6kk + j
        pRLT[(i*6 + (q % 6))*8 + (q / 6)] = make_float2(Rd[idx], Lu[idx]);
        // bias_u: sBuT[m*32 + l] = bu4[48*(l/8) + (l%8) + 8m]
        int m = idx / 32, ll = idx % 32;
        sBuT[idx] = bu2[48*(ll >> 3) + (ll & 7) + 8*m];
    }
    for (int idx = tid; idx < 64; idx += NT) {
        sRd[idx] = rule_d[idx];
        sRu[idx] = rule_u[idx];
    }
    __syncthreads();

    const int l = tid & 31;
    const int w = tid >> 5;
    const int g = l >> 3;        // group: a on input side, c on z/output side
    const int k = l & 7;

    float biasD[6];
#pragma unroll
    for (int j = 0; j < 6; j++)
        biasD[j] = bd[6*l + j];   // = bd[48g + 6k + j]

    const ulonglong2* x2 = (const ulonglong2*)x;
    char* outc = (char*)out;
    ulonglong2* stgW = stg + (size_t)w * (CHK * 192);
    const uint32_t stgW_s = (uint32_t)__cvta_generic_to_shared(stgW);

    const int gwarp = blockIdx.x * NW + w;
    const int nwarp = gridDim.x * NW;
    const int fbase = 48*g + k;  // lane's granule base (input AND output)

    for (int base = gwarp * TPI; base < ntok; base += nwarp * TPI) {
        int row[TPI];
#pragma unroll
        for (int tt = 0; tt < TPI; tt++) {
            int t = base + tt; if (t > ntok - 1) t = ntok - 1;
            row[tt] = t * 192 + fbase;
        }

        // ---- down stage 1: direct stride-8 loads (4 full 128B lines per
        //      LDG across the warp) + packed FMA ----
        u64 si2[TPI][4];
#pragma unroll
        for (int tt = 0; tt < TPI; tt++)
#pragma unroll
            for (int i = 0; i < 4; i++) si2[tt][i] = 0ull;

#pragma unroll
        for (int m = 0; m < 6; m++) {
            ulonglong2 u[TPI];
#pragma unroll
            for (int tt = 0; tt < TPI; tt++)
                u[tt] = x2[row[tt] + 8*m];
#pragma unroll
            for (int i = 0; i < 4; i++) {
                ulonglong2 wv = pLdT[(i*6 + m)*8 + k];   // 1-wf broadcast
#pragma unroll
                for (int tt = 0; tt < TPI; tt++) {
                    si2[tt][i] = fma2(u[tt].x, wv.x, si2[tt][i]);
                    si2[tt][i] = fma2(u[tt].y, wv.y, si2[tt][i]);
                }
            }
        }
        // butterfly within 8-lane groups -> group-uniform si
        float si[TPI][4];
#pragma unroll
        for (int tt = 0; tt < TPI; tt++)
#pragma unroll
            for (int i = 0; i < 4; i++) {
                float v = sum2(si2[tt][i]);
                v += __shfl_xor_sync(0xffffffffu, v, 4);
                v += __shfl_xor_sync(0xffffffffu, v, 2);
                v += __shfl_xor_sync(0xffffffffu, v, 1);
                si[tt][i] = v;
            }

        // ---- down stage 2: weighted rotate (3 SHFL per i) ----
        float tD[TPI][4];
#pragma unroll
        for (int tt = 0; tt < TPI; tt++)
#pragma unroll
            for (int i = 0; i < 4; i++)
                tD[tt][i] = sRd[i*16 + 5*g] * si[tt][i];
#pragma unroll
        for (int m = 1; m < 4; m++)
#pragma unroll
            for (int i = 0; i < 4; i++) {
                float r = sRd[i*16 + ((g ^ m) << 2) + g];
#pragma unroll
                for (int tt = 0; tt < TPI; tt++)
                    tD[tt][i] = fmaf(r, __shfl_xor_sync(0xffffffffu, si[tt][i], m*8),
                                     tD[tt][i]);
            }

        // ---- fused z -> gelu_new -> up stage 1 (s2); lane z: q = 6k+j ----
        float s2[TPI][4];
#pragma unroll
        for (int tt = 0; tt < TPI; tt++)
#pragma unroll
            for (int i = 0; i < 4; i++) s2[tt][i] = 0.f;

#pragma unroll
        for (int j = 0; j < 6; j++) {
            float2 rl[4];
#pragma unroll
            for (int i = 0; i < 4; i++) rl[i] = pRLT[(i*6 + j)*8 + k];
            float zv[TPI];
#pragma unroll
            for (int tt = 0; tt < TPI; tt++) zv[tt] = biasD[j];
#pragma unroll
            for (int i = 0; i < 4; i++)
#pragma unroll
                for (int tt = 0; tt < TPI; tt++)
                    zv[tt] = fmaf(tD[tt][i], rl[i].x, zv[tt]);
#pragma unroll
            for (int tt = 0; tt < TPI; tt++) {
                float z   = zv[tt];
                float arg = 0.7978845608028654f * fmaf(0.044715f*z, z*z, z);
                float h   = 0.5f * z;
                zv[tt] = fmaf(h, tanh_fast(arg), h);   // 0.5z(1+tanh)
            }
#pragma unroll
            for (int i = 0; i < 4; i++)
#pragma unroll
                for (int tt = 0; tt < TPI; tt++)
                    s2[tt][i] = fmaf(zv[tt], rl[i].y, s2[tt][i]);
        }
        // butterfly -> group-uniform s2
#pragma unroll
        for (int tt = 0; tt < TPI; tt++)
#pragma unroll
            for (int i = 0; i < 4; i++) {
                float v = s2[tt][i];
                v += __shfl_xor_sync(0xffffffffu, v, 4);
                v += __shfl_xor_sync(0xffffffffu, v, 2);
                v += __shfl_xor_sync(0xffffffffu, v, 1);
                s2[tt][i] = v;
            }

        // ---- up stage 2: weighted rotate ----
        float tU[TPI][4];
#pragma unroll
        for (int tt = 0; tt < TPI; tt++)
#pragma unroll
            for (int i = 0; i < 4; i++)
                tU[tt][i] = sRu[i*16 + 5*g] * s2[tt][i];
#pragma unroll
        for (int m = 1; m < 4; m++)
#pragma unroll
            for (int i = 0; i < 4; i++) {
                float r = sRu[i*16 + ((g ^ m) << 2) + g];
#pragma unroll
                for (int tt = 0; tt < TPI; tt++)
                    tU[tt][i] = fmaf(r, __shfl_xor_sync(0xffffffffu, s2[tt][i], m*8),
                                     tU[tt][i]);
            }

        // ---- output chunks: stride-8 compute -> linear conflict-free STS
        //      (bias folded in) -> TMA bulk store 3072B/token ----
#pragma unroll
        for (int c0 = 0; c0 < TPI; c0 += CHK) {
            u64 tUp[CHK][4];
#pragma unroll
            for (int cc = 0; cc < CHK; cc++)
#pragma unroll
                for (int i = 0; i < 4; i++)
                    tUp[cc][i] = pk2(tU[c0+cc][i], tU[c0+cc][i]);

            // previous chunk's TMA smem reads must finish before overwrite
            if (l == 0)
                asm volatile("cp.async.bulk.wait_group.read 0;" ::: "memory");
            __syncwarp();

#pragma unroll
            for (int m = 0; m < 6; m++) {
                ulonglong2 rv[4];
#pragma unroll
                for (int i = 0; i < 4; i++) rv[i] = pRuT[(i*6 + m)*8 + k];
                ulonglong2 bb = sBuT[m*32 + l];          // 1-wf, linear
#pragma unroll
                for (int cc = 0; cc < CHK; cc++) {
                    ulonglong2 o = bb;
#pragma unroll
                    for (int i = 0; i < 4; i++) {
                        o.x = fma2(tUp[cc][i], rv[i].x, o.x);
                        o.y = fma2(tUp[cc][i], rv[i].y, o.y);
                    }
                    stgW[cc*192 + fbase + 8*m] = o;      // linear, conflict-free
                }
            }
            __syncwarp();
            asm volatile("fence.proxy.async.shared::cta;" ::: "memory");
            if (l == 0) {
#pragma unroll
                for (int cc = 0; cc < CHK; cc++) {
                    int t = base + c0 + cc;
                    if (t < ntok)
                        bulk_store(outc + (size_t)t * 3072,
                                   stgW_s + cc * 3072, 3072);
                }
                asm volatile("cp.async.bulk.commit_group;" ::: "memory");
            }
        }
    }
    // drain outstanding bulk stores before exit
    if (l == 0)
        asm volatile("cp.async.bulk.wait_group 0;" ::: "memory");
}

extern "C" void kernel_launch(void* const* d_in, const int* in_sizes, int n_in,
                              void* d_out, int out_size)
{
    const float* x      = (const float*)d_in[0];
    const float* rule_d = (const float*)d_in[1];
    const float* Ld     = (const float*)d_in[2];
    const float* Rd     = (const float*)d_in[3];
    const float* bd     = (const float*)d_in[4];
    const float* rule_u = (const float*)d_in[5];
    const float* Lu     = (const float*)d_in[6];
    const float* Ru     = (const float*)d_in[7];
    const float* bu     = (const float*)d_in[8];

    const int ntok = in_sizes[0] / 768;

    cudaFuncSetAttribute(phm_fused_kernel,
                         cudaFuncAttributeMaxDynamicSharedMemorySize,
                         SMEM_TOTAL);

    // 148 SMs * 5 CTAs (128 thr, 35.8KB smem each) = one full wave
    phm_fused_kernel<<<740, NT, SMEM_TOTAL>>>(x, rule_d, Ld, Rd, bd,
                                              rule_u, Lu, Ru, bu,
                                              (float*)d_out, ntok);
}